// round 1
// baseline (speedup 1.0000x reference)
#include <cuda_runtime.h>
#include <cuda_bf16.h>
#include <cstdint>

// ---------------- problem constants ----------------
#define BSZ      4
#define CIN      128
#define HW       1024          // L = 32*32
#define DMODEL   256
#define DINNER   512
#define DSTATE   64
#define DTRANK   16
#define MTOT     (BSZ*HW)      // 4096

// ---------------- scratch (no cudaMalloc allowed) ----------------
__device__ float g_xt  [MTOT*CIN];       // x transposed (b,l,c)
__device__ float g_xseq[MTOT*DMODEL];    // residual
__device__ float g_xn  [MTOT*DMODEL];    // layernormed
__device__ float g_xz  [MTOT*2*DINNER];  // in_proj out: [:,0:512]=u_raw, [:,512:]=z
__device__ float g_u   [MTOT*DINNER];    // conv+silu out
__device__ float g_xdbl[MTOT*144];       // x_proj out (dt 16 | B 64 | C 64)
__device__ float g_dt  [MTOT*DINNER];    // delta (softplus)
__device__ float g_yg  [MTOT*DINNER];    // scan output, gated

__device__ __forceinline__ float fast_ex2(float x){
    float r; asm("ex2.approx.f32 %0, %1;" : "=f"(r) : "f"(x)); return r;
}

// ---------------- K0: transpose x (b,c,l) -> (b,l,c) ----------------
__global__ void transpose_kernel(const float* __restrict__ x, float* __restrict__ xt){
    __shared__ float tile[32][33];
    const int b  = blockIdx.z;
    const int c0 = blockIdx.y * 32;
    const int l0 = blockIdx.x * 32;
    const float* xb = x + (size_t)b * CIN * HW;
    #pragma unroll
    for (int i = 0; i < 4; i++)
        tile[threadIdx.y + 8*i][threadIdx.x] =
            xb[(size_t)(c0 + threadIdx.y + 8*i) * HW + l0 + threadIdx.x];
    __syncthreads();
    float* xtb = xt + (size_t)b * HW * CIN;
    #pragma unroll
    for (int i = 0; i < 4; i++)
        xtb[(size_t)(l0 + threadIdx.y + 8*i) * CIN + c0 + threadIdx.x] =
            tile[threadIdx.x][threadIdx.y + 8*i];
}

// ---------------- SGEMM: C[m,n] = sum_k A[m,k] * W[n,k]  (+ epilogue) ----------------
// EPI 0: plain store (stride N, guard n<N)
// EPI 1: add residual (stride 256) and store NCHW-transposed into out
template<int EPI>
__global__ void __launch_bounds__(256) sgemm(
    const float* __restrict__ A, const float* __restrict__ W,
    float* __restrict__ C, int M, int N, int K,
    const float* __restrict__ resid)
{
    constexpr int BM = 64, BN = 64, BK = 16;
    __shared__ float As[BK][BM + 4];
    __shared__ float Bs[BK][BN + 4];
    const int tid = threadIdx.x;
    const int bm = blockIdx.y * BM, bn = blockIdx.x * BN;
    const int lr = tid >> 2;          // 0..63
    const int lc = (tid & 3) << 2;    // 0,4,8,12
    const int tx = tid & 15, ty = tid >> 4;

    float acc[4][4];
    #pragma unroll
    for (int i = 0; i < 4; i++)
        #pragma unroll
        for (int j = 0; j < 4; j++) acc[i][j] = 0.f;

    const float* Aptr = A + (size_t)(bm + lr) * K + lc;
    const int nrow = bn + lr;
    const bool wok = nrow < N;
    const float* Wptr = W + (size_t)(wok ? nrow : 0) * K + lc;

    for (int k0 = 0; k0 < K; k0 += BK){
        float4 av = *(const float4*)(Aptr + k0);
        float4 bv = make_float4(0.f,0.f,0.f,0.f);
        if (wok) bv = *(const float4*)(Wptr + k0);
        As[lc+0][lr]=av.x; As[lc+1][lr]=av.y; As[lc+2][lr]=av.z; As[lc+3][lr]=av.w;
        Bs[lc+0][lr]=bv.x; Bs[lc+1][lr]=bv.y; Bs[lc+2][lr]=bv.z; Bs[lc+3][lr]=bv.w;
        __syncthreads();
        #pragma unroll
        for (int k = 0; k < BK; k++){
            float4 a = *(const float4*)&As[k][ty << 2];
            float4 b = *(const float4*)&Bs[k][tx << 2];
            float ar[4] = {a.x,a.y,a.z,a.w};
            float br[4] = {b.x,b.y,b.z,b.w};
            #pragma unroll
            for (int i = 0; i < 4; i++)
                #pragma unroll
                for (int j = 0; j < 4; j++)
                    acc[i][j] = fmaf(ar[i], br[j], acc[i][j]);
        }
        __syncthreads();
    }

    #pragma unroll
    for (int i = 0; i < 4; i++){
        const int m = bm + (ty << 2) + i;
        #pragma unroll
        for (int j = 0; j < 4; j++){
            const int n = bn + (tx << 2) + j;
            float v = acc[i][j];
            if (EPI == 0){
                if (n < N) C[(size_t)m * N + n] = v;
            } else {
                v += resid[(size_t)m * DMODEL + n];
                const int b = m >> 10, l = m & 1023;
                C[((size_t)(b * DMODEL + n) << 10) + l] = v;   // out[b,n,h,w]
            }
        }
    }
}

// ---------------- K2: LayerNorm over d_model=256 ----------------
__global__ void __launch_bounds__(256) ln_kernel(
    const float* __restrict__ xin, const float* __restrict__ g,
    const float* __restrict__ bta, float* __restrict__ xout)
{
    const int m = blockIdx.x;
    const int t = threadIdx.x;
    const float v = xin[(size_t)m * DMODEL + t];
    float s = v, q = v * v;
    #pragma unroll
    for (int o = 16; o; o >>= 1){
        s += __shfl_xor_sync(0xffffffffu, s, o);
        q += __shfl_xor_sync(0xffffffffu, q, o);
    }
    __shared__ float ss[8], sq[8];
    const int w = t >> 5;
    if ((t & 31) == 0){ ss[w] = s; sq[w] = q; }
    __syncthreads();
    s = 0.f; q = 0.f;
    #pragma unroll
    for (int i = 0; i < 8; i++){ s += ss[i]; q += sq[i]; }
    const float mu  = s * (1.f / DMODEL);
    const float var = q * (1.f / DMODEL) - mu * mu;
    const float r   = rsqrtf(var + 1e-5f);
    xout[(size_t)m * DMODEL + t] = (v - mu) * r * g[t] + bta[t];
}

// ---------------- K4: causal depthwise conv(4) + silu ----------------
__global__ void __launch_bounds__(256) conv_silu_kernel(
    const float* __restrict__ xz, const float* __restrict__ cw,
    const float* __restrict__ cb, float* __restrict__ u)
{
    const int idx = blockIdx.x * blockDim.x + threadIdx.x;   // MTOT*DINNER
    const int d = idx & (DINNER - 1);
    const int m = idx >> 9;
    const int l = m & (HW - 1);
    float acc = cb[d];
    #pragma unroll
    for (int k = 0; k < 4; k++){
        const int ls = l - 3 + k;
        if (ls >= 0)
            acc = fmaf(xz[(size_t)(m - 3 + k) * (2*DINNER) + d], cw[d*4 + k], acc);
    }
    const float sig = 1.f / (1.f + __expf(-acc));
    u[idx] = acc * sig;
}

// ---------------- K6: delta = softplus(dt @ dt_proj_w^T + b) ----------------
__global__ void __launch_bounds__(256) dt_kernel(
    const float* __restrict__ xdbl, const float* __restrict__ W,
    const float* __restrict__ bias, float* __restrict__ delta)
{
    const int idx = blockIdx.x * blockDim.x + threadIdx.x;   // MTOT*DINNER
    const int d = idx & (DINNER - 1);
    const int m = idx >> 9;
    const float4* xr = (const float4*)(xdbl + (size_t)m * 144);
    const float4* wr = (const float4*)(W + d * DTRANK);
    float acc = bias[d];
    #pragma unroll
    for (int i = 0; i < 4; i++){
        const float4 x4 = xr[i], w4 = wr[i];
        acc = fmaf(x4.x, w4.x, acc);
        acc = fmaf(x4.y, w4.y, acc);
        acc = fmaf(x4.z, w4.z, acc);
        acc = fmaf(x4.w, w4.w, acc);
    }
    delta[idx] = (acc > 20.f) ? acc : log1pf(__expf(acc));
}

// ---------------- K7: selective scan ----------------
// warp = 2 channels x 16 lanes, 4 states/lane. Block = 4 warps (8 channels).
// B/C staged through smem in 64-step chunks; shared 4-shfl reduction.
#define SC 64
__global__ void __launch_bounds__(128) scan_kernel(
    const float* __restrict__ xdbl, const float* __restrict__ delta,
    const float* __restrict__ u, const float* __restrict__ xz,
    const float* __restrict__ A_log, const float* __restrict__ Dvec,
    float* __restrict__ yg)
{
    __shared__ float bc[SC][128];        // [t][0:64]=B, [64:128]=C
    __shared__ float sdl[8][SC + 4];     // delta
    __shared__ float sdu[8][SC + 4];     // delta*u
    __shared__ float su [8][SC + 4];     // u
    __shared__ float sz [8][SC + 4];     // z

    const int tid  = threadIdx.x;
    const int b    = blockIdx.x >> 6;
    const int d0   = (blockIdx.x & 63) << 3;
    const int lane = tid & 31, w = tid >> 5;
    const int half = lane >> 4, ln = lane & 15;
    const int ch   = (w << 1) + half;
    const int d    = d0 + ch;
    const int sb   = ln << 2;

    float a2[4], h[4] = {0.f, 0.f, 0.f, 0.f};
    #pragma unroll
    for (int i = 0; i < 4; i++)
        a2[i] = -__expf(A_log[d * DSTATE + sb + i]) * 1.4426950408889634f;
    const float Dd = Dvec[d];
    const size_t mb = (size_t)b << 10;

    for (int l0 = 0; l0 < HW; l0 += SC){
        __syncthreads();
        // stage B|C rows (contiguous 128 floats at offset 16 of each xdbl row)
        for (int i = tid; i < SC * 32; i += 128){
            const int r = i >> 5, c4 = i & 31;
            const float4 v = *(const float4*)(xdbl + (mb + l0 + r) * 144 + 16 + (c4 << 2));
            *(float4*)&bc[r][c4 << 2] = v;
        }
        // stage per-channel scalars
        for (int i = tid; i < SC * 8; i += 128){
            const int t = i >> 3, c = i & 7;
            const size_t m = mb + l0 + t;
            const float dv = delta[m * DINNER + d0 + c];
            const float uv = u[m * DINNER + d0 + c];
            const float zv = xz[m * (2*DINNER) + DINNER + d0 + c];
            sdl[c][t] = dv;
            sdu[c][t] = dv * uv;
            su [c][t] = uv;
            sz [c][t] = zv;
        }
        __syncthreads();

        #pragma unroll 4
        for (int t = 0; t < SC; t++){
            const float dv = sdl[ch][t];
            const float du = sdu[ch][t];
            const float4 Bv = *(const float4*)&bc[t][sb];
            const float4 Cv = *(const float4*)&bc[t][64 + sb];
            const float e0 = fast_ex2(dv * a2[0]);
            const float e1 = fast_ex2(dv * a2[1]);
            const float e2 = fast_ex2(dv * a2[2]);
            const float e3 = fast_ex2(dv * a2[3]);
            h[0] = fmaf(e0, h[0], du * Bv.x);
            h[1] = fmaf(e1, h[1], du * Bv.y);
            h[2] = fmaf(e2, h[2], du * Bv.z);
            h[3] = fmaf(e3, h[3], du * Bv.w);
            float p = h[0]*Cv.x + h[1]*Cv.y + h[2]*Cv.z + h[3]*Cv.w;
            p += __shfl_xor_sync(0xffffffffu, p, 1);
            p += __shfl_xor_sync(0xffffffffu, p, 2);
            p += __shfl_xor_sync(0xffffffffu, p, 4);
            p += __shfl_xor_sync(0xffffffffu, p, 8);
            if (ln == 0){
                const float uu = su[ch][t], zz = sz[ch][t];
                const float yv = p + uu * Dd;
                const float sig = 1.f / (1.f + __expf(-zz));
                yg[(mb + l0 + t) * DINNER + d] = yv * (zz * sig);
            }
        }
    }
}

// ---------------- launch ----------------
extern "C" void kernel_launch(void* const* d_in, const int* in_sizes, int n_in,
                              void* d_out, int out_size)
{
    const float* x         = (const float*)d_in[0];
    const float* w_proj    = (const float*)d_in[1];
    const float* ln_g      = (const float*)d_in[2];
    const float* ln_b      = (const float*)d_in[3];
    const float* in_proj_w = (const float*)d_in[4];
    const float* conv_w    = (const float*)d_in[5];
    const float* conv_b    = (const float*)d_in[6];
    const float* x_proj_w  = (const float*)d_in[7];
    const float* dt_proj_w = (const float*)d_in[8];
    const float* dt_proj_b = (const float*)d_in[9];
    const float* A_log     = (const float*)d_in[10];
    const float* Dvec      = (const float*)d_in[11];
    const float* out_proj_w= (const float*)d_in[12];
    float* out = (float*)d_out;

    float *xt, *xseq, *xn, *xz, *u, *xdbl, *dt, *yg;
    cudaGetSymbolAddress((void**)&xt,   g_xt);
    cudaGetSymbolAddress((void**)&xseq, g_xseq);
    cudaGetSymbolAddress((void**)&xn,   g_xn);
    cudaGetSymbolAddress((void**)&xz,   g_xz);
    cudaGetSymbolAddress((void**)&u,    g_u);
    cudaGetSymbolAddress((void**)&xdbl, g_xdbl);
    cudaGetSymbolAddress((void**)&dt,   g_dt);
    cudaGetSymbolAddress((void**)&yg,   g_yg);

    // K0: transpose x -> (b,l,c)
    transpose_kernel<<<dim3(HW/32, CIN/32, BSZ), dim3(32, 8)>>>(x, xt);
    // K1: x_seq = xt @ w_proj^T
    sgemm<0><<<dim3(DMODEL/64, MTOT/64), 256>>>(xt, w_proj, xseq, MTOT, DMODEL, CIN, nullptr);
    // K2: layernorm
    ln_kernel<<<MTOT, 256>>>(xseq, ln_g, ln_b, xn);
    // K3: xz = xn @ in_proj_w^T
    sgemm<0><<<dim3((2*DINNER)/64, MTOT/64), 256>>>(xn, in_proj_w, xz, MTOT, 2*DINNER, DMODEL, nullptr);
    // K4: conv + silu
    conv_silu_kernel<<<(MTOT*DINNER)/256, 256>>>(xz, conv_w, conv_b, u);
    // K5: x_dbl = u @ x_proj_w^T   (N=144, guarded)
    sgemm<0><<<dim3(3, MTOT/64), 256>>>(u, x_proj_w, xdbl, MTOT, 144, DINNER, nullptr);
    // K6: delta
    dt_kernel<<<(MTOT*DINNER)/256, 256>>>(xdbl, dt_proj_w, dt_proj_b, dt);
    // K7: selective scan + gating
    scan_kernel<<<256, 128>>>(xdbl, dt, u, xz, A_log, Dvec, yg);
    // K8: out = yg @ out_proj_w^T + xseq, written NCHW
    sgemm<1><<<dim3(DMODEL/64, MTOT/64), 256>>>(yg, out_proj_w, out, MTOT, DMODEL, DINNER, xseq);
}